// round 1
// baseline (speedup 1.0000x reference)
#include <cuda_runtime.h>
#include <math.h>
#include <stdint.h>

// Problem dims (fixed by the dataset)
#define B_ 4
#define S_ 4096
#define E_ 1024
#define A_ 1024
#define M_ (B_ * S_)  // 16384 total rows

// Scratch (device globals: allocation-free rule)
__device__ float g_Q[(size_t)M_ * A_];            // 64 MB
__device__ float g_K[(size_t)M_ * A_];            // 64 MB
__device__ float g_V[(size_t)M_ * A_];            // 64 MB
__device__ float g_P[(size_t)B_ * S_ * S_];       // 256 MB scores/probs

// ---------------------------------------------------------------------------
// Tiled SGEMM config: 128x128 tile, BK=16, 256 threads, 8x8 per thread
// ---------------------------------------------------------------------------
#define BM 128
#define BN 128
#define BK 16

// ---------------------------------------------------------------------------
// Kernel 1: fused QKV projection.  Y = X @ W for W in {Wk, Wq, Wv}
// X: [16384, 1024] row-major, W: [1024, 1024] row-major
// grid: (A_/BN=8, M_/BM=128, 3)
// ---------------------------------------------------------------------------
__global__ __launch_bounds__(256, 2)
void qkv_kernel(const float* __restrict__ X,
                const float* __restrict__ Wk,
                const float* __restrict__ Wq,
                const float* __restrict__ Wv) {
    __shared__ float As[BK][BM];   // transposed A tile
    __shared__ float Bs[BK][BN];

    const int tid = threadIdx.x;
    const int ty = tid >> 4;       // 0..15
    const int tx = tid & 15;       // 0..15
    const int m0 = blockIdx.y * BM;
    const int n0 = blockIdx.x * BN;

    const float* W = (blockIdx.z == 0) ? Wk : (blockIdx.z == 1 ? Wq : Wv);
    float* Y = (blockIdx.z == 0) ? g_K : (blockIdx.z == 1 ? g_Q : g_V);

    float acc[8][8];
#pragma unroll
    for (int i = 0; i < 8; i++)
#pragma unroll
        for (int j = 0; j < 8; j++) acc[i][j] = 0.0f;

    for (int k0 = 0; k0 < E_; k0 += BK) {
        // Load A tile (transpose into smem): 128 rows x 16 cols = 512 float4
        {
            int i = tid;
#pragma unroll
            for (int it = 0; it < 2; it++, i += 256) {
                int r = i >> 2;              // 0..127
                int c4 = (i & 3) << 2;       // 0,4,8,12
                float4 v = *(const float4*)(X + (size_t)(m0 + r) * E_ + k0 + c4);
                As[c4 + 0][r] = v.x;
                As[c4 + 1][r] = v.y;
                As[c4 + 2][r] = v.z;
                As[c4 + 3][r] = v.w;
            }
            i = tid;
#pragma unroll
            for (int it = 0; it < 2; it++, i += 256) {
                int r = i >> 5;              // 0..15
                int c4 = (i & 31) << 2;      // 0..124
                *(float4*)&Bs[r][c4] =
                    *(const float4*)(W + (size_t)(k0 + r) * A_ + n0 + c4);
            }
        }
        __syncthreads();

#pragma unroll
        for (int kk = 0; kk < BK; kk++) {
            float a[8], b[8];
            *(float4*)&a[0] = *(const float4*)&As[kk][ty * 8];
            *(float4*)&a[4] = *(const float4*)&As[kk][ty * 8 + 4];
            *(float4*)&b[0] = *(const float4*)&Bs[kk][tx * 8];
            *(float4*)&b[4] = *(const float4*)&Bs[kk][tx * 8 + 4];
#pragma unroll
            for (int i = 0; i < 8; i++)
#pragma unroll
                for (int j = 0; j < 8; j++) acc[i][j] += a[i] * b[j];
        }
        __syncthreads();
    }

#pragma unroll
    for (int i = 0; i < 8; i++) {
        float* dst = Y + (size_t)(m0 + ty * 8 + i) * A_ + n0 + tx * 8;
        *(float4*)dst       = make_float4(acc[i][0], acc[i][1], acc[i][2], acc[i][3]);
        *(float4*)(dst + 4) = make_float4(acc[i][4], acc[i][5], acc[i][6], acc[i][7]);
    }
}

// ---------------------------------------------------------------------------
// Kernel 2: causal scores. P[b][q][k] = dot(Q[b,q,:], K[b,k,:]) / 32
// Only lower-tri tiles are computed. grid: (32 kt, 32 qt, 4 b)
// ---------------------------------------------------------------------------
__global__ __launch_bounds__(256, 2)
void scores_kernel() {
    const int kt = blockIdx.x;
    const int qt = blockIdx.y;
    if (kt > qt) return;
    const int b = blockIdx.z;

    const float* Q = g_Q + (size_t)b * S_ * A_;
    const float* K = g_K + (size_t)b * S_ * A_;
    float* P = g_P + (size_t)b * S_ * S_;

    const int tid = threadIdx.x;
    const int ty = tid >> 4;
    const int tx = tid & 15;
    const int q0 = qt * BM;
    const int k0 = kt * BN;

    __shared__ float Qs[BK][BM];
    __shared__ float Ks[BK][BN];

    float acc[8][8];
#pragma unroll
    for (int i = 0; i < 8; i++)
#pragma unroll
        for (int j = 0; j < 8; j++) acc[i][j] = 0.0f;

    for (int a0 = 0; a0 < A_; a0 += BK) {
        {
            int i = tid;
#pragma unroll
            for (int it = 0; it < 2; it++, i += 256) {
                int r = i >> 2;
                int c4 = (i & 3) << 2;
                float4 v = *(const float4*)(Q + (size_t)(q0 + r) * A_ + a0 + c4);
                Qs[c4 + 0][r] = v.x;
                Qs[c4 + 1][r] = v.y;
                Qs[c4 + 2][r] = v.z;
                Qs[c4 + 3][r] = v.w;
            }
            i = tid;
#pragma unroll
            for (int it = 0; it < 2; it++, i += 256) {
                int r = i >> 2;
                int c4 = (i & 3) << 2;
                float4 v = *(const float4*)(K + (size_t)(k0 + r) * A_ + a0 + c4);
                Ks[c4 + 0][r] = v.x;
                Ks[c4 + 1][r] = v.y;
                Ks[c4 + 2][r] = v.z;
                Ks[c4 + 3][r] = v.w;
            }
        }
        __syncthreads();

#pragma unroll
        for (int kk = 0; kk < BK; kk++) {
            float a[8], c[8];
            *(float4*)&a[0] = *(const float4*)&Qs[kk][ty * 8];
            *(float4*)&a[4] = *(const float4*)&Qs[kk][ty * 8 + 4];
            *(float4*)&c[0] = *(const float4*)&Ks[kk][tx * 8];
            *(float4*)&c[4] = *(const float4*)&Ks[kk][tx * 8 + 4];
#pragma unroll
            for (int i = 0; i < 8; i++)
#pragma unroll
                for (int j = 0; j < 8; j++) acc[i][j] += a[i] * c[j];
        }
        __syncthreads();
    }

    const float scale = 0.03125f;  // 1/sqrt(1024)
    if (qt > kt) {
        // fully below diagonal: vector stores
#pragma unroll
        for (int i = 0; i < 8; i++) {
            float* dst = P + (size_t)(q0 + ty * 8 + i) * S_ + k0 + tx * 8;
            *(float4*)dst = make_float4(acc[i][0] * scale, acc[i][1] * scale,
                                        acc[i][2] * scale, acc[i][3] * scale);
            *(float4*)(dst + 4) = make_float4(acc[i][4] * scale, acc[i][5] * scale,
                                              acc[i][6] * scale, acc[i][7] * scale);
        }
    } else {
        // diagonal tile: predicated scalar stores (k <= q only)
#pragma unroll
        for (int i = 0; i < 8; i++) {
            int q = q0 + ty * 8 + i;
#pragma unroll
            for (int j = 0; j < 8; j++) {
                int k = k0 + tx * 8 + j;
                if (k <= q) P[(size_t)q * S_ + k] = acc[i][j] * scale;
            }
        }
    }
}

// ---------------------------------------------------------------------------
// Kernel 3: row softmax over valid prefix [0, q], zero-fill (q, S).
// grid: (S_, B_), 256 threads, row cached in smem.
// ---------------------------------------------------------------------------
__global__ __launch_bounds__(256)
void softmax_kernel() {
    const int q = blockIdx.x;
    const int b = blockIdx.y;
    float* row = g_P + ((size_t)b * S_ + q) * S_;
    const int len = q + 1;
    const int tid = threadIdx.x;

    __shared__ float buf[S_];
    __shared__ float red[8];

    float m = -INFINITY;
    for (int i = tid; i < len; i += 256) {
        float v = row[i];
        buf[i] = v;
        m = fmaxf(m, v);
    }
#pragma unroll
    for (int o = 16; o; o >>= 1) m = fmaxf(m, __shfl_xor_sync(0xffffffffu, m, o));
    if ((tid & 31) == 0) red[tid >> 5] = m;
    __syncthreads();
    float mm = red[0];
#pragma unroll
    for (int w = 1; w < 8; w++) mm = fmaxf(mm, red[w]);

    float sum = 0.0f;
    for (int i = tid; i < len; i += 256) {
        float e = expf(buf[i] - mm);
        buf[i] = e;
        sum += e;
    }
#pragma unroll
    for (int o = 16; o; o >>= 1) sum += __shfl_xor_sync(0xffffffffu, sum, o);
    __syncthreads();  // red reuse guard
    if ((tid & 31) == 0) red[tid >> 5] = sum;
    __syncthreads();
    float tot = 0.0f;
#pragma unroll
    for (int w = 0; w < 8; w++) tot += red[w];
    const float inv = 1.0f / tot;

    for (int i = tid; i < len; i += 256) row[i] = buf[i] * inv;
    for (int i = len + tid; i < S_; i += 256) row[i] = 0.0f;
}

// ---------------------------------------------------------------------------
// Kernel 4: out = P @ V with causal tile bound, round(.,4) epilogue.
// grid: (A_/BN=8, S_/BM=32, B_)
// ---------------------------------------------------------------------------
__global__ __launch_bounds__(256, 2)
void pv_kernel(float* __restrict__ out) {
    const int nt = blockIdx.x;
    const int qt = blockIdx.y;
    const int b = blockIdx.z;

    const float* P = g_P + (size_t)b * S_ * S_;
    const float* V = g_V + (size_t)b * S_ * A_;
    float* O = out + (size_t)b * S_ * A_;

    const int tid = threadIdx.x;
    const int ty = tid >> 4;
    const int tx = tid & 15;
    const int m0 = qt * BM;
    const int n0 = nt * BN;
    const int kend = (qt + 1) * BM;   // probs are 0 beyond q; tiles beyond this are skipped

    __shared__ float As[BK][BM];
    __shared__ float Bs[BK][BN];

    float acc[8][8];
#pragma unroll
    for (int i = 0; i < 8; i++)
#pragma unroll
        for (int j = 0; j < 8; j++) acc[i][j] = 0.0f;

    for (int k0 = 0; k0 < kend; k0 += BK) {
        {
            int i = tid;
#pragma unroll
            for (int it = 0; it < 2; it++, i += 256) {
                int r = i >> 2;
                int c4 = (i & 3) << 2;
                float4 v = *(const float4*)(P + (size_t)(m0 + r) * S_ + k0 + c4);
                As[c4 + 0][r] = v.x;
                As[c4 + 1][r] = v.y;
                As[c4 + 2][r] = v.z;
                As[c4 + 3][r] = v.w;
            }
            i = tid;
#pragma unroll
            for (int it = 0; it < 2; it++, i += 256) {
                int r = i >> 5;
                int c4 = (i & 31) << 2;
                *(float4*)&Bs[r][c4] =
                    *(const float4*)(V + (size_t)(k0 + r) * A_ + n0 + c4);
            }
        }
        __syncthreads();

#pragma unroll
        for (int kk = 0; kk < BK; kk++) {
            float a[8], c[8];
            *(float4*)&a[0] = *(const float4*)&As[kk][ty * 8];
            *(float4*)&a[4] = *(const float4*)&As[kk][ty * 8 + 4];
            *(float4*)&c[0] = *(const float4*)&Bs[kk][tx * 8];
            *(float4*)&c[4] = *(const float4*)&Bs[kk][tx * 8 + 4];
#pragma unroll
            for (int i = 0; i < 8; i++)
#pragma unroll
                for (int j = 0; j < 8; j++) acc[i][j] += a[i] * c[j];
        }
        __syncthreads();
    }

    // round(out, 4): round-half-even like jnp.round
#pragma unroll
    for (int i = 0; i < 8; i++) {
        float r[8];
#pragma unroll
        for (int j = 0; j < 8; j++) r[j] = rintf(acc[i][j] * 1e4f) * 1e-4f;
        float* dst = O + (size_t)(m0 + ty * 8 + i) * A_ + n0 + tx * 8;
        *(float4*)dst       = make_float4(r[0], r[1], r[2], r[3]);
        *(float4*)(dst + 4) = make_float4(r[4], r[5], r[6], r[7]);
    }
}

// ---------------------------------------------------------------------------
extern "C" void kernel_launch(void* const* d_in, const int* in_sizes, int n_in,
                              void* d_out, int out_size) {
    const float* X  = (const float*)d_in[0];  // embedded [4,4096,1024]
    const float* Wk = (const float*)d_in[1];  // [1024,1024]
    const float* Wq = (const float*)d_in[2];
    const float* Wv = (const float*)d_in[3];
    float* out = (float*)d_out;               // [4,4096,1024] fp32

    dim3 blk(256);
    qkv_kernel<<<dim3(A_ / BN, M_ / BM, 3), blk>>>(X, Wk, Wq, Wv);
    scores_kernel<<<dim3(S_ / BN, S_ / BM, B_), blk>>>();
    softmax_kernel<<<dim3(S_, B_), blk>>>();
    pv_kernel<<<dim3(A_ / BN, S_ / BM, B_), blk>>>(out);
}

// round 3
// speedup vs baseline: 2.4268x; 2.4268x over previous
#include <cuda_runtime.h>
#include <cuda_bf16.h>
#include <math.h>
#include <stdint.h>

#define B_ 4
#define S_ 4096
#define E_ 1024
#define A_ 1024
#define M_ (B_ * S_)   // 16384

// ---------------------------------------------------------------------------
// Scratch (device globals; allocation-free rule)
// ---------------------------------------------------------------------------
__device__ __nv_bfloat16 g_Xhi[(size_t)M_ * E_];
__device__ __nv_bfloat16 g_Xlo[(size_t)M_ * E_];
__device__ __nv_bfloat16 g_Wthi[3][(size_t)E_ * A_];   // W transposed [a][e]
__device__ __nv_bfloat16 g_Wtlo[3][(size_t)E_ * A_];
__device__ __nv_bfloat16 g_Qhi[(size_t)M_ * A_];       // Q pre-scaled by 1/32
__device__ __nv_bfloat16 g_Qlo[(size_t)M_ * A_];
__device__ __nv_bfloat16 g_Khi[(size_t)M_ * A_];
__device__ __nv_bfloat16 g_Klo[(size_t)M_ * A_];
__device__ __nv_bfloat16 g_Vthi[(size_t)B_ * A_ * S_]; // V transposed [b][a][s]
__device__ __nv_bfloat16 g_Vtlo[(size_t)B_ * A_ * S_];
__device__ float         g_S[(size_t)B_ * S_ * S_];    // fp32 scores
__device__ __nv_bfloat16 g_Phi[(size_t)B_ * S_ * S_];  // probs hi
__device__ __nv_bfloat16 g_Plo[(size_t)B_ * S_ * S_];  // probs lo

// ---------------------------------------------------------------------------
// Baseline-PTX helpers (sm_103-safe: ldmatrix / mma.sync / cp.async)
// ---------------------------------------------------------------------------
static __device__ __forceinline__ uint32_t smem_u32(const void* p) {
    uint32_t a;
    asm("{ .reg .u64 t; cvta.to.shared.u64 t, %1; cvt.u32.u64 %0, t; }"
        : "=r"(a) : "l"(p));
    return a;
}

#define CP16(dst, src) \
    asm volatile("cp.async.cg.shared.global [%0], [%1], 16;" :: "r"(dst), "l"(src))
#define CP_COMMIT() asm volatile("cp.async.commit_group;" ::: "memory")
#define CP_WAIT1()  asm volatile("cp.async.wait_group 1;" ::: "memory")
#define CP_WAIT0()  asm volatile("cp.async.wait_group 0;" ::: "memory")

static __device__ __forceinline__ void ldm4(uint32_t r[4], uint32_t a) {
    asm volatile("ldmatrix.sync.aligned.m8n8.x4.shared.b16 {%0,%1,%2,%3}, [%4];"
                 : "=r"(r[0]), "=r"(r[1]), "=r"(r[2]), "=r"(r[3]) : "r"(a));
}

static __device__ __forceinline__ void mma16816(float d[4], const uint32_t a[4],
                                                uint32_t b0, uint32_t b1) {
    asm volatile(
        "mma.sync.aligned.m16n8k16.row.col.f32.bf16.bf16.f32 "
        "{%0,%1,%2,%3},{%4,%5,%6,%7},{%8,%9},{%0,%1,%2,%3};"
        : "+f"(d[0]), "+f"(d[1]), "+f"(d[2]), "+f"(d[3])
        : "r"(a[0]), "r"(a[1]), "r"(a[2]), "r"(a[3]), "r"(b0), "r"(b1));
}

// Tiles: 128 rows x 64B (32 bf16). Swizzle: 16B-chunk ^= row[2:1] (conflict-free
// for both the cp.async fill and all ldmatrix phases).
// Stage = 4 tiles (Ahi, Alo, Bhi, Blo) = 32 KB; two stages = 64 KB.
#define TILE_B   8192
#define STAGE_B  32768

// ---------------------------------------------------------------------------
// Mainloop: acc[2][4][4] (warp tile 32x32) += sum over chunks (BK=32) of
//   Ahi*Bhi^T + Ahi*Blo^T + Alo*Bhi^T    (bf16 inputs, fp32 accum)
// A: [128 rows m][k] k-contig (lda elems), B: [128 rows n][k] k-contig.
// ---------------------------------------------------------------------------
static __device__ __forceinline__ void mma_loop(
    uint32_t sb,
    const __nv_bfloat16* __restrict__ Ahi, const __nv_bfloat16* __restrict__ Alo, int lda,
    const __nv_bfloat16* __restrict__ Bhi, const __nv_bfloat16* __restrict__ Blo, int ldb,
    int nchunk, float acc[2][4][4])
{
    const int tid = threadIdx.x;
    const int lane = tid & 31, wid = tid >> 5;
    const int wm = wid & 3, wn = wid >> 2;

    // fill mapping: each thread moves one 16B chunk per tile per stage
    const int fr = tid >> 2, fc = tid & 3;
    const uint32_t fdst = (uint32_t)(fr * 64) |
                          (((uint32_t)fc * 16u) ^ ((((uint32_t)fr >> 1) & 3u) << 4));
    const size_t fAo = (size_t)fr * lda + fc * 8;
    const size_t fBo = (size_t)fr * ldb + fc * 8;

    // ldmatrix per-lane base addrs (chunk-xor trick: addr for k-byte kb = p ^ kb)
    const uint32_t lhA = (lane & 16) ? 16u : 0u;
    const int rA0 = wm * 32 + (lane & 15), rA1 = rA0 + 16;
    const uint32_t pA0 = (uint32_t)(rA0 * 64) | (lhA ^ ((((uint32_t)rA0 >> 1) & 3u) << 4));
    const uint32_t pA1 = (uint32_t)(rA1 * 64) | (lhA ^ ((((uint32_t)rA1 >> 1) & 3u) << 4));
    const uint32_t lhB = (lane & 8) ? 16u : 0u;
    const int rB0 = wn * 32 + ((lane & 16) ? 8 : 0) + (lane & 7), rB1 = rB0 + 16;
    const uint32_t pB0 = (uint32_t)(rB0 * 64) | (lhB ^ ((((uint32_t)rB0 >> 1) & 3u) << 4));
    const uint32_t pB1 = (uint32_t)(rB1 * 64) | (lhB ^ ((((uint32_t)rB1 >> 1) & 3u) << 4));

    auto fill = [&](int c, int st) {
        const uint32_t base = sb + (uint32_t)st * STAGE_B;
        const size_t ko = (size_t)c * 32;
        CP16(base + fdst,              (const char*)(Ahi + fAo + ko));
        CP16(base + TILE_B + fdst,     (const char*)(Alo + fAo + ko));
        CP16(base + 2 * TILE_B + fdst, (const char*)(Bhi + fBo + ko));
        CP16(base + 3 * TILE_B + fdst, (const char*)(Blo + fBo + ko));
        CP_COMMIT();
    };

    fill(0, 0);
    for (int c = 0; c < nchunk; c++) {
        if (c + 1 < nchunk) { fill(c + 1, (c + 1) & 1); CP_WAIT1(); }
        else                { CP_WAIT0(); }
        __syncthreads();

        const uint32_t tb = sb + (uint32_t)(c & 1) * STAGE_B;
#pragma unroll
        for (int s = 0; s < 2; s++) {
            const uint32_t kb = (uint32_t)s * 32u;
            uint32_t ah0[4], ah1[4], al0[4], al1[4];
            ldm4(ah0, tb + (pA0 ^ kb));
            ldm4(ah1, tb + (pA1 ^ kb));
            ldm4(al0, tb + TILE_B + (pA0 ^ kb));
            ldm4(al1, tb + TILE_B + (pA1 ^ kb));
#pragma unroll
            for (int g = 0; g < 2; g++) {
                const uint32_t pb = g ? pB1 : pB0;
                uint32_t bh[4], bl[4];
                ldm4(bh, tb + 2 * TILE_B + (pb ^ kb));
                ldm4(bl, tb + 3 * TILE_B + (pb ^ kb));
                mma16816(acc[0][g * 2 + 0], ah0, bh[0], bh[1]);
                mma16816(acc[1][g * 2 + 0], ah1, bh[0], bh[1]);
                mma16816(acc[0][g * 2 + 1], ah0, bh[2], bh[3]);
                mma16816(acc[1][g * 2 + 1], ah1, bh[2], bh[3]);
                mma16816(acc[0][g * 2 + 0], ah0, bl[0], bl[1]);
                mma16816(acc[1][g * 2 + 0], ah1, bl[0], bl[1]);
                mma16816(acc[0][g * 2 + 1], ah0, bl[2], bl[3]);
                mma16816(acc[1][g * 2 + 1], ah1, bl[2], bl[3]);
                mma16816(acc[0][g * 2 + 0], al0, bh[0], bh[1]);
                mma16816(acc[1][g * 2 + 0], al1, bh[0], bh[1]);
                mma16816(acc[0][g * 2 + 1], al0, bh[2], bh[3]);
                mma16816(acc[1][g * 2 + 1], al1, bh[2], bh[3]);
            }
        }
        __syncthreads();
    }
}

// fragment coords: row = base + wm*32 + mi*16 + lane/4 (+8 for regs 2,3)
//                  col = base + wn*32 + nj*8 + (lane%4)*2

// ---------------------------------------------------------------------------
// QKV: z=0 -> K, z=1 -> Q (scaled 1/32), z=2 -> V (transposed store)
// grid (8, 128, 3), 512 threads
// ---------------------------------------------------------------------------
__global__ __launch_bounds__(512, 1)
void qkv_mma_kernel() {
    extern __shared__ char smem[];
    const uint32_t sb = smem_u32(smem);
    const int z = blockIdx.z, m0 = blockIdx.y * 128, n0 = blockIdx.x * 128;

    float acc[2][4][4] = {};
    mma_loop(sb, g_Xhi + (size_t)m0 * E_, g_Xlo + (size_t)m0 * E_, E_,
             g_Wthi[z] + (size_t)n0 * E_, g_Wtlo[z] + (size_t)n0 * E_, E_,
             E_ / 32, acc);

    const int lane = threadIdx.x & 31, wid = threadIdx.x >> 5;
    const int wm = wid & 3, wn = wid >> 2;
    const float scale = (z == 1) ? 0.03125f : 1.0f;

    if (z != 2) {
        __nv_bfloat16* dhi = z ? g_Qhi : g_Khi;
        __nv_bfloat16* dlo = z ? g_Qlo : g_Klo;
#pragma unroll
        for (int mi = 0; mi < 2; mi++)
#pragma unroll
            for (int nj = 0; nj < 4; nj++)
#pragma unroll
                for (int h = 0; h < 2; h++) {
                    int r = m0 + wm * 32 + mi * 16 + (lane >> 2) + h * 8;
                    int cc = n0 + wn * 32 + nj * 8 + (lane & 3) * 2;
                    float v0 = acc[mi][nj][h * 2 + 0] * scale;
                    float v1 = acc[mi][nj][h * 2 + 1] * scale;
                    __nv_bfloat16 h0 = __float2bfloat16(v0);
                    __nv_bfloat16 h1 = __float2bfloat16(v1);
                    __nv_bfloat162 hv; hv.x = h0; hv.y = h1;
                    __nv_bfloat162 lv;
                    lv.x = __float2bfloat16(v0 - __bfloat162float(h0));
                    lv.y = __float2bfloat16(v1 - __bfloat162float(h1));
                    size_t off = (size_t)r * A_ + cc;
                    *(__nv_bfloat162*)(dhi + off) = hv;
                    *(__nv_bfloat162*)(dlo + off) = lv;
                }
    } else {
        // transpose through smem: tile (m=s, n=a) -> Vt[a][s]
        __nv_bfloat16* tHi = (__nv_bfloat16*)smem;              // [128][136]
        __nv_bfloat16* tLo = (__nv_bfloat16*)(smem + 34816);
#pragma unroll
        for (int mi = 0; mi < 2; mi++)
#pragma unroll
            for (int nj = 0; nj < 4; nj++)
#pragma unroll
                for (int h = 0; h < 2; h++) {
                    int ml = wm * 32 + mi * 16 + (lane >> 2) + h * 8;
                    int cl = wn * 32 + nj * 8 + (lane & 3) * 2;
                    float v0 = acc[mi][nj][h * 2 + 0];
                    float v1 = acc[mi][nj][h * 2 + 1];
                    __nv_bfloat16 h0 = __float2bfloat16(v0);
                    __nv_bfloat16 h1 = __float2bfloat16(v1);
                    tHi[cl * 136 + ml] = h0;
                    tHi[(cl + 1) * 136 + ml] = h1;
                    tLo[cl * 136 + ml] = __float2bfloat16(v0 - __bfloat162float(h0));
                    tLo[(cl + 1) * 136 + ml] = __float2bfloat16(v1 - __bfloat162float(h1));
                }
        __syncthreads();
        const int b = m0 >> 12, s0 = m0 & 4095;
        const int rr = threadIdx.x >> 2, cg = threadIdx.x & 3;
        const uint4* shi = (const uint4*)(smem + rr * 272 + cg * 64);
        const uint4* slo = (const uint4*)(smem + 34816 + rr * 272 + cg * 64);
        uint4* dhi = (uint4*)(g_Vthi + ((size_t)b * A_ + n0 + rr) * S_ + s0 + cg * 32);
        uint4* dlo = (uint4*)(g_Vtlo + ((size_t)b * A_ + n0 + rr) * S_ + s0 + cg * 32);
#pragma unroll
        for (int j = 0; j < 4; j++) { dhi[j] = shi[j]; dlo[j] = slo[j]; }
    }
}

// ---------------------------------------------------------------------------
// Scores: S[b][q][k] = (Q/32) . K   (lower-tri tiles only)
// grid (32 kt, 32 qt, 4 b), 512 threads
// ---------------------------------------------------------------------------
__global__ __launch_bounds__(512, 1)
void scores_mma_kernel() {
    const int kt = blockIdx.x, qt = blockIdx.y;
    if (kt > qt) return;
    const int b = blockIdx.z;
    extern __shared__ char smem[];
    const uint32_t sb = smem_u32(smem);
    const int q0 = qt * 128, k0 = kt * 128;

    float acc[2][4][4] = {};
    const size_t ao = (size_t)(b * S_ + q0) * A_;
    const size_t bo = (size_t)(b * S_ + k0) * A_;
    mma_loop(sb, g_Qhi + ao, g_Qlo + ao, A_, g_Khi + bo, g_Klo + bo, A_,
             A_ / 32, acc);

    const int lane = threadIdx.x & 31, wid = threadIdx.x >> 5;
    const int wm = wid & 3, wn = wid >> 2;
    float* P = g_S + (size_t)b * S_ * S_;
    const bool full = (kt < qt);
#pragma unroll
    for (int mi = 0; mi < 2; mi++)
#pragma unroll
        for (int nj = 0; nj < 4; nj++)
#pragma unroll
            for (int h = 0; h < 2; h++) {
                int q = q0 + wm * 32 + mi * 16 + (lane >> 2) + h * 8;
                int k = k0 + wn * 32 + nj * 8 + (lane & 3) * 2;
                float v0 = acc[mi][nj][h * 2 + 0];
                float v1 = acc[mi][nj][h * 2 + 1];
                if (full) {
                    *(float2*)(P + (size_t)q * S_ + k) = make_float2(v0, v1);
                } else {
                    if (k <= q)     P[(size_t)q * S_ + k] = v0;
                    if (k + 1 <= q) P[(size_t)q * S_ + k + 1] = v1;
                }
            }
}

// ---------------------------------------------------------------------------
// Softmax over prefix [0,q] -> bf16 hi/lo probs, zero-fill beyond.
// grid (4096, 4), 256 threads
// ---------------------------------------------------------------------------
__global__ __launch_bounds__(256)
void softmax_kernel() {
    const int q = blockIdx.x, b = blockIdx.y;
    const float* row = g_S + ((size_t)b * S_ + q) * S_;
    __nv_bfloat16* ohi = g_Phi + ((size_t)b * S_ + q) * S_;
    __nv_bfloat16* olo = g_Plo + ((size_t)b * S_ + q) * S_;
    const int len = q + 1;
    const int tid = threadIdx.x;

    __shared__ float fbuf[S_];
    __shared__ float red[8];

    float m = -INFINITY;
    for (int i = tid; i < len; i += 256) {
        float v = row[i];
        fbuf[i] = v;
        m = fmaxf(m, v);
    }
#pragma unroll
    for (int o = 16; o; o >>= 1) m = fmaxf(m, __shfl_xor_sync(0xffffffffu, m, o));
    if ((tid & 31) == 0) red[tid >> 5] = m;
    __syncthreads();
    float mm = red[0];
#pragma unroll
    for (int w = 1; w < 8; w++) mm = fmaxf(mm, red[w]);

    float sum = 0.0f;
    for (int i = tid; i < len; i += 256) {
        float e = expf(fbuf[i] - mm);
        fbuf[i] = e;
        sum += e;
    }
#pragma unroll
    for (int o = 16; o; o >>= 1) sum += __shfl_xor_sync(0xffffffffu, sum, o);
    __syncthreads();
    if ((tid & 31) == 0) red[tid >> 5] = sum;
    __syncthreads();
    float tot = 0.0f;
#pragma unroll
    for (int w = 0; w < 8; w++) tot += red[w];
    const float inv = 1.0f / tot;

    const __nv_bfloat16 z = __float2bfloat16(0.0f);
    for (int i = tid; i < len; i += 256) {
        float p = fbuf[i] * inv;
        __nv_bfloat16 h = __float2bfloat16(p);
        ohi[i] = h;
        olo[i] = __float2bfloat16(p - __bfloat162float(h));
    }
    for (int i = len + tid; i < S_; i += 256) { ohi[i] = z; olo[i] = z; }
}

// ---------------------------------------------------------------------------
// PV: out = P @ Vt^T with causal k-bound, round(.,4).
// grid (8 at, 32 qt, 4 b), 512 threads
// ---------------------------------------------------------------------------
__global__ __launch_bounds__(512, 1)
void pv_mma_kernel(float* __restrict__ out) {
    const int at = blockIdx.x, qt = blockIdx.y, b = blockIdx.z;
    extern __shared__ char smem[];
    const uint32_t sb = smem_u32(smem);
    const int q0 = qt * 128, n0 = at * 128;

    float acc[2][4][4] = {};
    const size_t ao = (size_t)(b * S_ + q0) * S_;
    const size_t bo = ((size_t)b * A_ + n0) * S_;
    mma_loop(sb, g_Phi + ao, g_Plo + ao, S_, g_Vthi + bo, g_Vtlo + bo, S_,
             (qt + 1) * 4, acc);

    const int lane = threadIdx.x & 31, wid = threadIdx.x >> 5;
    const int wm = wid & 3, wn = wid >> 2;
#pragma unroll
    for (int mi = 0; mi < 2; mi++)
#pragma unroll
        for (int nj = 0; nj < 4; nj++)
#pragma unroll
            for (int h = 0; h < 2; h++) {
                int r = q0 + wm * 32 + mi * 16 + (lane >> 2) + h * 8;
                int cc = n0 + wn * 32 + nj * 8 + (lane & 3) * 2;
                float v0 = rintf(acc[mi][nj][h * 2 + 0] * 1e4f) * 1e-4f;
                float v1 = rintf(acc[mi][nj][h * 2 + 1] * 1e4f) * 1e-4f;
                *(float2*)(out + (size_t)(b * S_ + r) * A_ + cc) = make_float2(v0, v1);
            }
}

// ---------------------------------------------------------------------------
// Conversions
// ---------------------------------------------------------------------------
__global__ __launch_bounds__(256)
void cvt_x_kernel(const float* __restrict__ src) {
    int i = blockIdx.x * 256 + threadIdx.x;
    if (i < M_ * E_) {
        float v = src[i];
        __nv_bfloat16 h = __float2bfloat16(v);
        g_Xhi[i] = h;
        g_Xlo[i] = __float2bfloat16(v - __bfloat162float(h));
    }
}

__global__ __launch_bounds__(256)
void cvt_w_kernel(const float* __restrict__ src, int which) {
    int i = blockIdx.x * 256 + threadIdx.x;
    if (i < E_ * A_) {
        int k = i >> 10, n = i & 1023;
        float v = src[(size_t)k * A_ + n];
        __nv_bfloat16 h = __float2bfloat16(v);
        size_t off = (size_t)n * E_ + k;
        g_Wthi[which][off] = h;
        g_Wtlo[which][off] = __float2bfloat16(v - __bfloat162float(h));
    }
}

// ---------------------------------------------------------------------------
#define SMEM_MAIN 65536
#define SMEM_QKV  69632   // mainloop 64KB, V-transpose epilogue 69632

extern "C" void kernel_launch(void* const* d_in, const int* in_sizes, int n_in,
                              void* d_out, int out_size) {
    const float* X  = (const float*)d_in[0];
    const float* Wk = (const float*)d_in[1];
    const float* Wq = (const float*)d_in[2];
    const float* Wv = (const float*)d_in[3];
    float* out = (float*)d_out;

    cudaFuncSetAttribute(qkv_mma_kernel,
                         cudaFuncAttributeMaxDynamicSharedMemorySize, SMEM_QKV);
    cudaFuncSetAttribute(scores_mma_kernel,
                         cudaFuncAttributeMaxDynamicSharedMemorySize, SMEM_MAIN);
    cudaFuncSetAttribute(pv_mma_kernel,
                         cudaFuncAttributeMaxDynamicSharedMemorySize, SMEM_MAIN);

    cvt_x_kernel<<<(M_ * E_ + 255) / 256, 256>>>(X);
    cvt_w_kernel<<<(E_ * A_ + 255) / 256, 256>>>(Wk, 0);
    cvt_w_kernel<<<(E_ * A_ + 255) / 256, 256>>>(Wq, 1);
    cvt_w_kernel<<<(E_ * A_ + 255) / 256, 256>>>(Wv, 2);

    qkv_mma_kernel<<<dim3(A_ / 128, M_ / 128, 3), 512, SMEM_QKV>>>();
    scores_mma_kernel<<<dim3(S_ / 128, S_ / 128, B_), 512, SMEM_MAIN>>>();
    softmax_kernel<<<dim3(S_, B_), 256>>>();
    pv_mma_kernel<<<dim3(A_ / 128, S_ / 128, B_), 512, SMEM_MAIN>>>(out);
}

// round 5
// speedup vs baseline: 2.5916x; 1.0679x over previous
#include <cuda_runtime.h>
#include <cuda_bf16.h>
#include <math.h>
#include <stdint.h>

#define B_ 4
#define S_ 4096
#define E_ 1024
#define A_ 1024
#define M_ (B_ * S_)   // 16384

// ---------------------------------------------------------------------------
// Scratch (device globals; allocation-free rule)
// ---------------------------------------------------------------------------
__device__ __nv_bfloat16 g_Xhi[(size_t)M_ * E_];
__device__ __nv_bfloat16 g_Xlo[(size_t)M_ * E_];
__device__ __nv_bfloat16 g_Wthi[3][(size_t)E_ * A_];   // W transposed [a][e]
__device__ __nv_bfloat16 g_Wtlo[3][(size_t)E_ * A_];
__device__ __nv_bfloat16 g_Qhi[(size_t)M_ * A_];       // Q pre-scaled 1/32
__device__ __nv_bfloat16 g_Qlo[(size_t)M_ * A_];
__device__ __nv_bfloat16 g_Khi[(size_t)M_ * A_];
__device__ __nv_bfloat16 g_Klo[(size_t)M_ * A_];
__device__ __nv_bfloat16 g_Vthi[(size_t)B_ * A_ * S_]; // V transposed [b][a][s]
__device__ __nv_bfloat16 g_Vtlo[(size_t)B_ * A_ * S_];
__device__ float         g_S[(size_t)B_ * S_ * S_];    // fp32 scores
__device__ __nv_bfloat16 g_Phi[(size_t)B_ * S_ * S_];  // probs hi
__device__ __nv_bfloat16 g_Plo[(size_t)B_ * S_ * S_];  // probs lo

// ---------------------------------------------------------------------------
// Baseline-PTX helpers
// ---------------------------------------------------------------------------
static __device__ __forceinline__ uint32_t smem_u32(const void* p) {
    uint32_t a;
    asm("{ .reg .u64 t; cvta.to.shared.u64 t, %1; cvt.u32.u64 %0, t; }"
        : "=r"(a) : "l"(p));
    return a;
}

#define CP16(dst, src) \
    asm volatile("cp.async.cg.shared.global [%0], [%1], 16;" :: "r"(dst), "l"(src))
#define CP_COMMIT() asm volatile("cp.async.commit_group;" ::: "memory")
#define CP_WAIT2()  asm volatile("cp.async.wait_group 2;" ::: "memory")
#define CP_WAIT1()  asm volatile("cp.async.wait_group 1;" ::: "memory")
#define CP_WAIT0()  asm volatile("cp.async.wait_group 0;" ::: "memory")

static __device__ __forceinline__ void ldm4(uint32_t r[4], uint32_t a) {
    asm volatile("ldmatrix.sync.aligned.m8n8.x4.shared.b16 {%0,%1,%2,%3}, [%4];"
                 : "=r"(r[0]), "=r"(r[1]), "=r"(r[2]), "=r"(r[3]) : "r"(a));
}

static __device__ __forceinline__ void mma16816(float d[4], const uint32_t a[4],
                                                uint32_t b0, uint32_t b1) {
    asm volatile(
        "mma.sync.aligned.m16n8k16.row.col.f32.bf16.bf16.f32 "
        "{%0,%1,%2,%3},{%4,%5,%6,%7},{%8,%9},{%0,%1,%2,%3};"
        : "+f"(d[0]), "+f"(d[1]), "+f"(d[2]), "+f"(d[3])
        : "r"(a[0]), "r"(a[1]), "r"(a[2]), "r"(a[3]), "r"(b0), "r"(b1));
}

// Tile rows are 64B (32 bf16, BK=32); 16B-chunk swizzle: c ^= row[2:1].
static __device__ __forceinline__ uint32_t sw_off(uint32_t r, uint32_t c) {
    return (r * 64u) | (((c ^ ((r >> 1) & 3u)) & 3u) * 16u);
}

// ---------------------------------------------------------------------------
// Mainloop (256 threads, 8 warps). CTA tile 128m x BNn, BK=32, 3-stage ring.
// Warp layout: wm = wid&1 (64 m rows), wn = wid>>1 (BN/4 n cols).
// acc[4][BN/32][4]: D += Ahi*Bhi^T + Ahi*Blo^T + Alo*Bhi^T  (fp32 accum)
// A: [128 m][k] k-contig (lda), B: [BN n][k] k-contig (ldb).
// ---------------------------------------------------------------------------
template <int BN>
static __device__ __forceinline__ void mma_loop(
    uint32_t sb,
    const __nv_bfloat16* __restrict__ Ahi, const __nv_bfloat16* __restrict__ Alo, int lda,
    const __nv_bfloat16* __restrict__ Bhi, const __nv_bfloat16* __restrict__ Blo, int ldb,
    int nchunk, float acc[4][BN / 32][4])
{
    constexpr int NG = BN / 64;              // n16 groups per warp
    constexpr uint32_t TILE_A = 8192;        // 128 x 64B
    constexpr uint32_t TILE_BB = (uint32_t)BN * 64;
    constexpr uint32_t OFF_ALO = TILE_A;
    constexpr uint32_t OFF_BHI = 2 * TILE_A;
    constexpr uint32_t OFF_BLO = 2 * TILE_A + TILE_BB;
    constexpr uint32_t STAGE = 2 * TILE_A + 2 * TILE_BB;

    const int tid = threadIdx.x;
    const int lane = tid & 31, wid = tid >> 5;
    const int wm = wid & 1, wn = wid >> 1;

    // ldmatrix per-lane base addrs
    uint32_t pA[4];
#pragma unroll
    for (int mi = 0; mi < 4; mi++) {
        uint32_t rA = wm * 64 + mi * 16 + (lane & 15);
        uint32_t lh = (lane & 16) ? 16u : 0u;
        pA[mi] = (rA * 64u) | (lh ^ (((rA >> 1) & 3u) << 4));
    }
    uint32_t pB[NG];
#pragma unroll
    for (int g = 0; g < NG; g++) {
        uint32_t rB = wn * (BN / 4) + g * 16 + ((lane & 16) ? 8 : 0) + (lane & 7);
        uint32_t lh = (lane & 8) ? 16u : 0u;
        pB[g] = (rB * 64u) | (lh ^ (((rB >> 1) & 3u) << 4));
    }

    auto fill = [&](int c) {
        const uint32_t base = sb + (uint32_t)(c % 3) * STAGE;
        const size_t ko = (size_t)c * 32;
#pragma unroll
        for (int i = 0; i < 2; i++) {                 // A tiles: 512 chunks each
            uint32_t ch = tid + i * 256;
            uint32_t r = ch >> 2, cc = ch & 3;
            uint32_t d = sw_off(r, cc);
            const size_t go = (size_t)r * lda + cc * 8 + ko;
            CP16(base + d,           (const char*)(Ahi + go));
            CP16(base + OFF_ALO + d, (const char*)(Alo + go));
        }
#pragma unroll
        for (int i = 0; i < BN / 64; i++) {           // B tiles: BN*4 chunks each
            uint32_t ch = tid + i * 256;
            uint32_t r = ch >> 2, cc = ch & 3;
            uint32_t d = sw_off(r, cc);
            const size_t go = (size_t)r * ldb + cc * 8 + ko;
            CP16(base + OFF_BHI + d, (const char*)(Bhi + go));
            CP16(base + OFF_BLO + d, (const char*)(Blo + go));
        }
        CP_COMMIT();
    };

    if (0 < nchunk) fill(0);
    if (1 < nchunk) fill(1);
    if (2 < nchunk) fill(2);

    for (int c = 0; c < nchunk; c++) {
        const int rem = nchunk - c;
        if (rem >= 3) CP_WAIT2();
        else if (rem == 2) CP_WAIT1();
        else CP_WAIT0();
        __syncthreads();

        const uint32_t tb = sb + (uint32_t)(c % 3) * STAGE;
#pragma unroll
        for (int s = 0; s < 2; s++) {
            const uint32_t kb = (uint32_t)s * 32u;
            uint32_t ah[4][4], al[4][4];
#pragma unroll
            for (int mi = 0; mi < 4; mi++) {
                ldm4(ah[mi], tb + (pA[mi] ^ kb));
                ldm4(al[mi], tb + OFF_ALO + (pA[mi] ^ kb));
            }
#pragma unroll
            for (int g = 0; g < NG; g++) {
                uint32_t bh[4], bl[4];
                ldm4(bh, tb + OFF_BHI + (pB[g] ^ kb));
                ldm4(bl, tb + OFF_BLO + (pB[g] ^ kb));
#pragma unroll
                for (int mi = 0; mi < 4; mi++) {
                    mma16816(acc[mi][g * 2 + 0], ah[mi], bh[0], bh[1]);
                    mma16816(acc[mi][g * 2 + 1], ah[mi], bh[2], bh[3]);
                    mma16816(acc[mi][g * 2 + 0], ah[mi], bl[0], bl[1]);
                    mma16816(acc[mi][g * 2 + 1], ah[mi], bl[2], bl[3]);
                    mma16816(acc[mi][g * 2 + 0], al[mi], bh[0], bh[1]);
                    mma16816(acc[mi][g * 2 + 1], al[mi], bh[2], bh[3]);
                }
            }
        }
        __syncthreads();
        if (c + 3 < nchunk) fill(c + 3);   // reuses stage just consumed
    }
}

// fragment coords (8-warp layout): row = wm*64 + mi*16 + lane/4 + h*8
//                                  col = wn*(BN/4) + nj*8 + (lane%4)*2

#define SMEM_128  98304    // 3 stages x 32KB
#define SMEM_256  147456   // 3 stages x 48KB

// ---------------------------------------------------------------------------
// QKV: z=0 -> K, z=1 -> Q (scaled 1/32), z=2 -> V (transposed store)
// grid (8, 128, 3), 256 threads
// ---------------------------------------------------------------------------
__global__ __launch_bounds__(256, 1)
void qkv_mma_kernel() {
    extern __shared__ char smem[];
    const uint32_t sb = smem_u32(smem);
    const int z = blockIdx.z, m0 = blockIdx.y * 128, n0 = blockIdx.x * 128;

    float acc[4][4][4] = {};
    mma_loop<128>(sb, g_Xhi + (size_t)m0 * E_, g_Xlo + (size_t)m0 * E_, E_,
                  g_Wthi[z] + (size_t)n0 * E_, g_Wtlo[z] + (size_t)n0 * E_, E_,
                  E_ / 32, acc);

    const int lane = threadIdx.x & 31, wid = threadIdx.x >> 5;
    const int wm = wid & 1, wn = wid >> 1;
    const float scale = (z == 1) ? 0.03125f : 1.0f;

    if (z != 2) {
        __nv_bfloat16* dhi = z ? g_Qhi : g_Khi;
        __nv_bfloat16* dlo = z ? g_Qlo : g_Klo;
#pragma unroll
        for (int mi = 0; mi < 4; mi++)
#pragma unroll
            for (int nj = 0; nj < 4; nj++)
#pragma unroll
                for (int h = 0; h < 2; h++) {
                    int r = m0 + wm * 64 + mi * 16 + (lane >> 2) + h * 8;
                    int cc = n0 + wn * 32 + nj * 8 + (lane & 3) * 2;
                    float v0 = acc[mi][nj][h * 2 + 0] * scale;
                    float v1 = acc[mi][nj][h * 2 + 1] * scale;
                    __nv_bfloat16 h0 = __float2bfloat16(v0);
                    __nv_bfloat16 h1 = __float2bfloat16(v1);
                    __nv_bfloat162 hv; hv.x = h0; hv.y = h1;
                    __nv_bfloat162 lv;
                    lv.x = __float2bfloat16(v0 - __bfloat162float(h0));
                    lv.y = __float2bfloat16(v1 - __bfloat162float(h1));
                    size_t off = (size_t)r * A_ + cc;
                    *(__nv_bfloat162*)(dhi + off) = hv;
                    *(__nv_bfloat162*)(dlo + off) = lv;
                }
    } else {
        // transpose tile (m=s, n=a) -> Vt[a][s] through smem [128a][136s]
        __nv_bfloat16* tHi = (__nv_bfloat16*)smem;
        __nv_bfloat16* tLo = (__nv_bfloat16*)(smem + 34816);
        __syncthreads();
#pragma unroll
        for (int mi = 0; mi < 4; mi++)
#pragma unroll
            for (int nj = 0; nj < 4; nj++)
#pragma unroll
                for (int h = 0; h < 2; h++) {
                    int ml = wm * 64 + mi * 16 + (lane >> 2) + h * 8;
                    int cl = wn * 32 + nj * 8 + (lane & 3) * 2;
                    float v0 = acc[mi][nj][h * 2 + 0];
                    float v1 = acc[mi][nj][h * 2 + 1];
                    __nv_bfloat16 h0 = __float2bfloat16(v0);
                    __nv_bfloat16 h1 = __float2bfloat16(v1);
                    tHi[cl * 136 + ml] = h0;
                    tHi[(cl + 1) * 136 + ml] = h1;
                    tLo[cl * 136 + ml] = __float2bfloat16(v0 - __bfloat162float(h0));
                    tLo[(cl + 1) * 136 + ml] = __float2bfloat16(v1 - __bfloat162float(h1));
                }
        __syncthreads();
        const int b = m0 >> 12, s0 = m0 & 4095;
        const int rr = threadIdx.x >> 1, cg = threadIdx.x & 1;   // a-row, s-half
        const uint4* shi = (const uint4*)(smem + rr * 272 + cg * 128);
        const uint4* slo = (const uint4*)(smem + 34816 + rr * 272 + cg * 128);
        uint4* dhi = (uint4*)(g_Vthi + ((size_t)b * A_ + n0 + rr) * S_ + s0 + cg * 64);
        uint4* dlo = (uint4*)(g_Vtlo + ((size_t)b * A_ + n0 + rr) * S_ + s0 + cg * 64);
#pragma unroll
        for (int j = 0; j < 8; j++) { dhi[j] = shi[j]; dlo[j] = slo[j]; }
    }
}

// ---------------------------------------------------------------------------
// Scores: S[b][q][k] = (Q/32) . K   (lower-tri tiles only)
// grid (32 kt, 32 qt, 4 b), 256 threads
// ---------------------------------------------------------------------------
__global__ __launch_bounds__(256, 1)
void scores_mma_kernel() {
    const int kt = blockIdx.x, qt = blockIdx.y;
    if (kt > qt) return;
    const int b = blockIdx.z;
    extern __shared__ char smem[];
    const uint32_t sb = smem_u32(smem);
    const int q0 = qt * 128, k0 = kt * 128;

    float acc[4][4][4] = {};
    const size_t ao = (size_t)(b * S_ + q0) * A_;
    const size_t bo = (size_t)(b * S_ + k0) * A_;
    mma_loop<128>(sb, g_Qhi + ao, g_Qlo + ao, A_, g_Khi + bo, g_Klo + bo, A_,
                  A_ / 32, acc);

    const int lane = threadIdx.x & 31, wid = threadIdx.x >> 5;
    const int wm = wid & 1, wn = wid >> 1;
    float* P = g_S + (size_t)b * S_ * S_;
    const bool full = (kt < qt);
#pragma unroll
    for (int mi = 0; mi < 4; mi++)
#pragma unroll
        for (int nj = 0; nj < 4; nj++)
#pragma unroll
            for (int h = 0; h < 2; h++) {
                int q = q0 + wm * 64 + mi * 16 + (lane >> 2) + h * 8;
                int k = k0 + wn * 32 + nj * 8 + (lane & 3) * 2;
                float v0 = acc[mi][nj][h * 2 + 0];
                float v1 = acc[mi][nj][h * 2 + 1];
                if (full) {
                    *(float2*)(P + (size_t)q * S_ + k) = make_float2(v0, v1);
                } else {
                    if (k <= q)     P[(size_t)q * S_ + k] = v0;
                    if (k + 1 <= q) P[(size_t)q * S_ + k + 1] = v1;
                }
            }
}

// ---------------------------------------------------------------------------
// Softmax over prefix [0,q] -> bf16 hi/lo probs; zero-fill only to the
// 128-aligned bound PV reads.
// grid (4096, 4), 256 threads
// ---------------------------------------------------------------------------
__global__ __launch_bounds__(256)
void softmax_kernel() {
    const int q = blockIdx.x, b = blockIdx.y;
    const float* row = g_S + ((size_t)b * S_ + q) * S_;
    __nv_bfloat16* ohi = g_Phi + ((size_t)b * S_ + q) * S_;
    __nv_bfloat16* olo = g_Plo + ((size_t)b * S_ + q) * S_;
    const int len = q + 1;
    const int zend = ((q >> 7) + 1) << 7;
    const int tid = threadIdx.x;

    __shared__ float fbuf[S_];
    __shared__ float red[8];

    float m = -INFINITY;
    for (int i = tid; i < len; i += 256) {
        float v = row[i];
        fbuf[i] = v;
        m = fmaxf(m, v);
    }
#pragma unroll
    for (int o = 16; o; o >>= 1) m = fmaxf(m, __shfl_xor_sync(0xffffffffu, m, o));
    if ((tid & 31) == 0) red[tid >> 5] = m;
    __syncthreads();
    float mm = red[0];
#pragma unroll
    for (int w = 1; w < 8; w++) mm = fmaxf(mm, red[w]);

    float sum = 0.0f;
    for (int i = tid; i < len; i += 256) {
        float e = expf(fbuf[i] - mm);
        fbuf[i] = e;
        sum += e;
    }
#pragma unroll
    for (int o = 16; o; o >>= 1) sum += __shfl_xor_sync(0xffffffffu, sum, o);
    __syncthreads();
    if ((tid & 31) == 0) red[tid >> 5] = sum;
    __syncthreads();
    float tot = 0.0f;
#pragma unroll
    for (int w = 0; w < 8; w++) tot += red[w];
    const float inv = 1.0f / tot;

    const __nv_bfloat16 z = __float2bfloat16(0.0f);
    for (int i = tid; i < len; i += 256) {
        float p = fbuf[i] * inv;
        __nv_bfloat16 h = __float2bfloat16(p);
        ohi[i] = h;
        olo[i] = __float2bfloat16(p - __bfloat162float(h));
    }
    for (int i = len + tid; i < zend; i += 256) { ohi[i] = z; olo[i] = z; }
}

// ---------------------------------------------------------------------------
// PV: out = P @ Vt^T (128q x 256a per CTA), causal k-bound, round(.,4).
// grid (4 at, 32 qt, 4 b), 256 threads
// ---------------------------------------------------------------------------
__global__ __launch_bounds__(256, 1)
void pv_mma_kernel(float* __restrict__ out) {
    const int at = blockIdx.x, qt = blockIdx.y, b = blockIdx.z;
    extern __shared__ char smem[];
    const uint32_t sb = smem_u32(smem);
    const int q0 = qt * 128, n0 = at * 256;

    float acc[4][8][4] = {};
    const size_t ao = (size_t)(b * S_ + q0) * S_;
    const size_t bo = ((size_t)b * A_ + n0) * S_;
    mma_loop<256>(sb, g_Phi + ao, g_Plo + ao, S_, g_Vthi + bo, g_Vtlo + bo, S_,
                  (qt + 1) * 4, acc);

    const int lane = threadIdx.x & 31, wid = threadIdx.x >> 5;
    const int wm = wid & 1, wn = wid >> 1;
#pragma unroll
    for (int mi = 0; mi < 4; mi++)
#pragma unroll
        for (int nj = 0; nj < 8; nj++)
#pragma unroll
            for (int h = 0; h < 2; h++) {
                int r = q0 + wm * 64 + mi * 16 + (lane >> 2) + h * 8;
                int cc = n0 + wn * 64 + nj * 8 + (lane & 3) * 2;
                float v0 = rintf(acc[mi][nj][h * 2 + 0] * 1e4f) * 1e-4f;
                float v1 = rintf(acc[mi][nj][h * 2 + 1] * 1e4f) * 1e-4f;
                *(float2*)(out + (size_t)(b * S_ + r) * A_ + cc) = make_float2(v0, v1);
            }
}

// ---------------------------------------------------------------------------
// Conversions
// ---------------------------------------------------------------------------
__global__ __launch_bounds__(256)
void cvt_x_kernel(const float* __restrict__ src) {
    int i = (blockIdx.x * 256 + threadIdx.x) * 4;
    float4 v = *(const float4*)(src + i);
    __nv_bfloat162 h0, h1, l0, l1;
    h0.x = __float2bfloat16(v.x); h0.y = __float2bfloat16(v.y);
    h1.x = __float2bfloat16(v.z); h1.y = __float2bfloat16(v.w);
    l0.x = __float2bfloat16(v.x - __bfloat162float(h0.x));
    l0.y = __float2bfloat16(v.y - __bfloat162float(h0.y));
    l1.x = __float2bfloat16(v.z - __bfloat162float(h1.x));
    l1.y = __float2bfloat16(v.w - __bfloat162float(h1.y));
    *(__nv_bfloat162*)(g_Xhi + i) = h0;
    *(__nv_bfloat162*)(g_Xhi + i + 2) = h1;
    *(__nv_bfloat162*)(g_Xlo + i) = l0;
    *(__nv_bfloat162*)(g_Xlo + i + 2) = l1;
}

// Tiled transpose: W[e][a] -> Wt[a][e] hi/lo. grid (32, 32, 3), 256 threads.
__global__ __launch_bounds__(256)
void cvt_w_kernel(const float* __restrict__ Wk, const float* __restrict__ Wq,
                  const float* __restrict__ Wv) {
    const int which = blockIdx.z;
    const float* src = which == 0 ? Wk : (which == 1 ? Wq : Wv);
    const int a0 = blockIdx.x * 32, e0 = blockIdx.y * 32;
    __shared__ float t[32][33];

    const int r = threadIdx.x >> 5, c = threadIdx.x & 31;
#pragma unroll
    for (int i = 0; i < 4; i++)
        t[r + i * 8][c] = src[(size_t)(e0 + r + i * 8) * A_ + a0 + c];
    __syncthreads();

    const int r2 = threadIdx.x >> 4, c2 = (threadIdx.x & 15) * 2;
#pragma unroll
    for (int i = 0; i < 2; i++) {
        int ar = r2 + i * 16;
        float v0 = t[c2][ar], v1 = t[c2 + 1][ar];
        __nv_bfloat162 hv, lv;
        hv.x = __float2bfloat16(v0); hv.y = __float2bfloat16(v1);
        lv.x = __float2bfloat16(v0 - __bfloat162float(hv.x));
        lv.y = __float2bfloat16(v1 - __bfloat162float(hv.y));
        size_t off = (size_t)(a0 + ar) * E_ + e0 + c2;
        *(__nv_bfloat162*)(g_Wthi[which] + off) = hv;
        *(__nv_bfloat162*)(g_Wtlo[which] + off) = lv;
    }
}

// ---------------------------------------------------------------------------
extern "C" void kernel_launch(void* const* d_in, const int* in_sizes, int n_in,
                              void* d_out, int out_size) {
    const float* X  = (const float*)d_in[0];
    const float* Wk = (const float*)d_in[1];
    const float* Wq = (const float*)d_in[2];
    const float* Wv = (const float*)d_in[3];
    float* out = (float*)d_out;

    cudaFuncSetAttribute(qkv_mma_kernel,
                         cudaFuncAttributeMaxDynamicSharedMemorySize, SMEM_128);
    cudaFuncSetAttribute(scores_mma_kernel,
                         cudaFuncAttributeMaxDynamicSharedMemorySize, SMEM_128);
    cudaFuncSetAttribute(pv_mma_kernel,
                         cudaFuncAttributeMaxDynamicSharedMemorySize, SMEM_256);

    cvt_x_kernel<<<M_ * E_ / 1024, 256>>>(X);
    cvt_w_kernel<<<dim3(32, 32, 3), 256>>>(Wk, Wq, Wv);

    qkv_mma_kernel<<<dim3(A_ / 128, M_ / 128, 3), 256, SMEM_128>>>();
    scores_mma_kernel<<<dim3(S_ / 128, S_ / 128, B_), 256, SMEM_128>>>();
    softmax_kernel<<<dim3(S_, B_), 256>>>();
    pv_mma_kernel<<<dim3(A_ / 256, S_ / 128, B_), 256, SMEM_256>>>(out);
}

// round 6
// speedup vs baseline: 2.7886x; 1.0760x over previous
#include <cuda_runtime.h>
#include <cuda_bf16.h>
#include <math.h>
#include <stdint.h>

#define B_ 4
#define S_ 4096
#define E_ 1024
#define A_ 1024
#define M_ (B_ * S_)   // 16384

// ---------------------------------------------------------------------------
// Scratch (device globals; allocation-free rule)
// ---------------------------------------------------------------------------
__device__ __nv_bfloat16 g_Xhi[(size_t)M_ * E_];
__device__ __nv_bfloat16 g_Xlo[(size_t)M_ * E_];
__device__ __nv_bfloat16 g_Wthi[3][(size_t)E_ * A_];   // W transposed [a][e]
__device__ __nv_bfloat16 g_Wtlo[3][(size_t)E_ * A_];
__device__ __nv_bfloat16 g_Qhi[(size_t)M_ * A_];       // Q pre-scaled 1/32
__device__ __nv_bfloat16 g_Qlo[(size_t)M_ * A_];
__device__ __nv_bfloat16 g_Khi[(size_t)M_ * A_];
__device__ __nv_bfloat16 g_Klo[(size_t)M_ * A_];
__device__ __nv_bfloat16 g_Vthi[(size_t)B_ * A_ * S_]; // V transposed [b][a][s]
__device__ __nv_bfloat16 g_Vtlo[(size_t)B_ * A_ * S_];
__device__ float         g_S[(size_t)B_ * S_ * S_];    // fp32 scores
__device__ __nv_bfloat16 g_Phi[(size_t)B_ * S_ * S_];  // probs hi
__device__ __nv_bfloat16 g_Plo[(size_t)B_ * S_ * S_];  // probs lo

// ---------------------------------------------------------------------------
// Baseline-PTX helpers
// ---------------------------------------------------------------------------
static __device__ __forceinline__ uint32_t smem_u32(const void* p) {
    uint32_t a;
    asm("{ .reg .u64 t; cvta.to.shared.u64 t, %1; cvt.u32.u64 %0, t; }"
        : "=r"(a) : "l"(p));
    return a;
}

#define CP16(dst, src) \
    asm volatile("cp.async.cg.shared.global [%0], [%1], 16;" :: "r"(dst), "l"(src))
#define CP_COMMIT() asm volatile("cp.async.commit_group;" ::: "memory")
#define CP_WAIT2()  asm volatile("cp.async.wait_group 2;" ::: "memory")
#define CP_WAIT1()  asm volatile("cp.async.wait_group 1;" ::: "memory")
#define CP_WAIT0()  asm volatile("cp.async.wait_group 0;" ::: "memory")

static __device__ __forceinline__ void ldm4(uint32_t r[4], uint32_t a) {
    asm volatile("ldmatrix.sync.aligned.m8n8.x4.shared.b16 {%0,%1,%2,%3}, [%4];"
                 : "=r"(r[0]), "=r"(r[1]), "=r"(r[2]), "=r"(r[3]) : "r"(a));
}

static __device__ __forceinline__ void mma16816(float d[4], const uint32_t a[4],
                                                uint32_t b0, uint32_t b1) {
    asm volatile(
        "mma.sync.aligned.m16n8k16.row.col.f32.bf16.bf16.f32 "
        "{%0,%1,%2,%3},{%4,%5,%6,%7},{%8,%9},{%0,%1,%2,%3};"
        : "+f"(d[0]), "+f"(d[1]), "+f"(d[2]), "+f"(d[3])
        : "r"(a[0]), "r"(a[1]), "r"(a[2]), "r"(a[3]), "r"(b0), "r"(b1));
}

// Tile rows are 64B (32 bf16, BK=32); 16B-chunk swizzle: c ^= row[2:1].
static __device__ __forceinline__ uint32_t sw_off(uint32_t r, uint32_t c) {
    return (r * 64u) | (((c ^ ((r >> 1) & 3u)) & 3u) * 16u);
}

// ---------------------------------------------------------------------------
// Mainloop (256 threads, 8 warps). CTA tile 128m x BNn, BK=32, NST-stage ring.
// NST==2: two syncs per chunk (stage reused immediately after compute).
// NST==4: ONE sync per chunk — fill(c+3) writes the stage consumed at c-1,
//         which the top-of-iter barrier already protects.
// Warp layout: wm = wid&1 (64 m rows), wn = wid>>1 (BN/4 n cols).
// acc[4][BN/32][4]: D += Ahi*Bhi^T + Ahi*Blo^T + Alo*Bhi^T  (fp32 accum)
// ---------------------------------------------------------------------------
template <int BN, int NST>
static __device__ __forceinline__ void mma_loop(
    uint32_t sb,
    const __nv_bfloat16* __restrict__ Ahi, const __nv_bfloat16* __restrict__ Alo, int lda,
    const __nv_bfloat16* __restrict__ Bhi, const __nv_bfloat16* __restrict__ Blo, int ldb,
    int nchunk, float acc[4][BN / 32][4])
{
    constexpr int NG = BN / 64;              // n16 groups per warp
    constexpr uint32_t TILE_A = 8192;        // 128 x 64B
    constexpr uint32_t TILE_BB = (uint32_t)BN * 64;
    constexpr uint32_t OFF_ALO = TILE_A;
    constexpr uint32_t OFF_BHI = 2 * TILE_A;
    constexpr uint32_t OFF_BLO = 2 * TILE_A + TILE_BB;
    constexpr uint32_t STAGE = 2 * TILE_A + 2 * TILE_BB;
    // fill-ahead distance: NST for two-sync, NST-1 for one-sync
    constexpr int AHEAD = (NST == 4) ? NST - 1 : NST;

    const int tid = threadIdx.x;
    const int lane = tid & 31, wid = tid >> 5;
    const int wm = wid & 1, wn = wid >> 1;

    // ldmatrix per-lane base addrs
    uint32_t pA[4];
#pragma unroll
    for (int mi = 0; mi < 4; mi++) {
        uint32_t rA = wm * 64 + mi * 16 + (lane & 15);
        uint32_t lh = (lane & 16) ? 16u : 0u;
        pA[mi] = (rA * 64u) | (lh ^ (((rA >> 1) & 3u) << 4));
    }
    uint32_t pB[NG];
#pragma unroll
    for (int g = 0; g < NG; g++) {
        uint32_t rB = wn * (BN / 4) + g * 16 + ((lane & 16) ? 8 : 0) + (lane & 7);
        uint32_t lh = (lane & 8) ? 16u : 0u;
        pB[g] = (rB * 64u) | (lh ^ (((rB >> 1) & 3u) << 4));
    }

    auto fill = [&](int c) {
        const uint32_t base = sb + (uint32_t)(c % NST) * STAGE;
        const size_t ko = (size_t)c * 32;
#pragma unroll
        for (int i = 0; i < 2; i++) {                 // A tiles: 512 chunks each
            uint32_t ch = tid + i * 256;
            uint32_t r = ch >> 2, cc = ch & 3;
            uint32_t d = sw_off(r, cc);
            const size_t go = (size_t)r * lda + cc * 8 + ko;
            CP16(base + d,           (const char*)(Ahi + go));
            CP16(base + OFF_ALO + d, (const char*)(Alo + go));
        }
#pragma unroll
        for (int i = 0; i < BN / 64; i++) {           // B tiles: BN*4 chunks each
            uint32_t ch = tid + i * 256;
            uint32_t r = ch >> 2, cc = ch & 3;
            uint32_t d = sw_off(r, cc);
            const size_t go = (size_t)r * ldb + cc * 8 + ko;
            CP16(base + OFF_BHI + d, (const char*)(Bhi + go));
            CP16(base + OFF_BLO + d, (const char*)(Blo + go));
        }
        CP_COMMIT();
    };

#pragma unroll
    for (int p = 0; p < AHEAD; p++)
        if (p < nchunk) fill(p);

    for (int c = 0; c < nchunk; c++) {
        // committed groups so far = min(nchunk, c + AHEAD); need stage c done
        const int outa = (nchunk < c + AHEAD ? nchunk : c + AHEAD) - c - 1;
        if (outa >= 2) CP_WAIT2();
        else if (outa == 1) CP_WAIT1();
        else CP_WAIT0();
        __syncthreads();

        if (NST == 4) {
            if (c + AHEAD < nchunk) fill(c + AHEAD);
        }

        const uint32_t tb = sb + (uint32_t)(c % NST) * STAGE;
#pragma unroll
        for (int s = 0; s < 2; s++) {
            const uint32_t kb = (uint32_t)s * 32u;
            uint32_t ah[4][4], al[4][4];
#pragma unroll
            for (int mi = 0; mi < 4; mi++) {
                ldm4(ah[mi], tb + (pA[mi] ^ kb));
                ldm4(al[mi], tb + OFF_ALO + (pA[mi] ^ kb));
            }
#pragma unroll
            for (int g = 0; g < NG; g++) {
                uint32_t bh[4], bl[4];
                ldm4(bh, tb + OFF_BHI + (pB[g] ^ kb));
                ldm4(bl, tb + OFF_BLO + (pB[g] ^ kb));
#pragma unroll
                for (int mi = 0; mi < 4; mi++) {
                    mma16816(acc[mi][g * 2 + 0], ah[mi], bh[0], bh[1]);
                    mma16816(acc[mi][g * 2 + 1], ah[mi], bh[2], bh[3]);
                    mma16816(acc[mi][g * 2 + 0], ah[mi], bl[0], bl[1]);
                    mma16816(acc[mi][g * 2 + 1], ah[mi], bl[2], bl[3]);
                    mma16816(acc[mi][g * 2 + 0], al[mi], bh[0], bh[1]);
                    mma16816(acc[mi][g * 2 + 1], al[mi], bh[2], bh[3]);
                }
            }
        }

        if (NST == 2) {
            __syncthreads();
            if (c + AHEAD < nchunk) fill(c + AHEAD);
        }
    }
}

// fragment coords (8-warp layout): row = wm*64 + mi*16 + lane/4 + h*8
//                                  col = wn*(BN/4) + nj*8 + (lane%4)*2

#define SMEM_QKV    69632    // 2 stages x 32KB (mainloop); 69632 for V-epilogue
#define SMEM_SCORES 65536    // 2 stages x 32KB
#define SMEM_PV     196608   // 4 stages x 48KB

// ---------------------------------------------------------------------------
// QKV: z=0 -> K, z=1 -> Q (scaled 1/32), z=2 -> V (transposed store)
// grid (8, 128, 3), 256 threads, 2 CTAs/SM
// ---------------------------------------------------------------------------
__global__ __launch_bounds__(256, 2)
void qkv_mma_kernel() {
    extern __shared__ char smem[];
    const uint32_t sb = smem_u32(smem);
    const int z = blockIdx.z, m0 = blockIdx.y * 128, n0 = blockIdx.x * 128;

    float acc[4][4][4] = {};
    mma_loop<128, 2>(sb, g_Xhi + (size_t)m0 * E_, g_Xlo + (size_t)m0 * E_, E_,
                     g_Wthi[z] + (size_t)n0 * E_, g_Wtlo[z] + (size_t)n0 * E_, E_,
                     E_ / 32, acc);

    const int lane = threadIdx.x & 31, wid = threadIdx.x >> 5;
    const int wm = wid & 1, wn = wid >> 1;
    const float scale = (z == 1) ? 0.03125f : 1.0f;

    if (z != 2) {
        __nv_bfloat16* dhi = z ? g_Qhi : g_Khi;
        __nv_bfloat16* dlo = z ? g_Qlo : g_Klo;
#pragma unroll
        for (int mi = 0; mi < 4; mi++)
#pragma unroll
            for (int nj = 0; nj < 4; nj++)
#pragma unroll
                for (int h = 0; h < 2; h++) {
                    int r = m0 + wm * 64 + mi * 16 + (lane >> 2) + h * 8;
                    int cc = n0 + wn * 32 + nj * 8 + (lane & 3) * 2;
                    float v0 = acc[mi][nj][h * 2 + 0] * scale;
                    float v1 = acc[mi][nj][h * 2 + 1] * scale;
                    __nv_bfloat16 h0 = __float2bfloat16(v0);
                    __nv_bfloat16 h1 = __float2bfloat16(v1);
                    __nv_bfloat162 hv; hv.x = h0; hv.y = h1;
                    __nv_bfloat162 lv;
                    lv.x = __float2bfloat16(v0 - __bfloat162float(h0));
                    lv.y = __float2bfloat16(v1 - __bfloat162float(h1));
                    size_t off = (size_t)r * A_ + cc;
                    *(__nv_bfloat162*)(dhi + off) = hv;
                    *(__nv_bfloat162*)(dlo + off) = lv;
                }
    } else {
        // transpose tile (m=s, n=a) -> Vt[a][s] through smem [128a][136s]
        __nv_bfloat16* tHi = (__nv_bfloat16*)smem;
        __nv_bfloat16* tLo = (__nv_bfloat16*)(smem + 34816);
        __syncthreads();
#pragma unroll
        for (int mi = 0; mi < 4; mi++)
#pragma unroll
            for (int nj = 0; nj < 4; nj++)
#pragma unroll
                for (int h = 0; h < 2; h++) {
                    int ml = wm * 64 + mi * 16 + (lane >> 2) + h * 8;
                    int cl = wn * 32 + nj * 8 + (lane & 3) * 2;
                    float v0 = acc[mi][nj][h * 2 + 0];
                    float v1 = acc[mi][nj][h * 2 + 1];
                    __nv_bfloat16 h0 = __float2bfloat16(v0);
                    __nv_bfloat16 h1 = __float2bfloat16(v1);
                    tHi[cl * 136 + ml] = h0;
                    tHi[(cl + 1) * 136 + ml] = h1;
                    tLo[cl * 136 + ml] = __float2bfloat16(v0 - __bfloat162float(h0));
                    tLo[(cl + 1) * 136 + ml] = __float2bfloat16(v1 - __bfloat162float(h1));
                }
        __syncthreads();
        const int b = m0 >> 12, s0 = m0 & 4095;
        const int rr = threadIdx.x >> 1, cg = threadIdx.x & 1;   // a-row, s-half
        const uint4* shi = (const uint4*)(smem + rr * 272 + cg * 128);
        const uint4* slo = (const uint4*)(smem + 34816 + rr * 272 + cg * 128);
        uint4* dhi = (uint4*)(g_Vthi + ((size_t)b * A_ + n0 + rr) * S_ + s0 + cg * 64);
        uint4* dlo = (uint4*)(g_Vtlo + ((size_t)b * A_ + n0 + rr) * S_ + s0 + cg * 64);
#pragma unroll
        for (int j = 0; j < 8; j++) { dhi[j] = shi[j]; dlo[j] = slo[j]; }
    }
}

// ---------------------------------------------------------------------------
// Scores: S[b][q][k] = (Q/32) . K   (lower-tri tiles only)
// grid (32 kt, 32 qt, 4 b), 256 threads, 2 CTAs/SM
// ---------------------------------------------------------------------------
__global__ __launch_bounds__(256, 2)
void scores_mma_kernel() {
    const int kt = blockIdx.x, qt = blockIdx.y;
    if (kt > qt) return;
    const int b = blockIdx.z;
    extern __shared__ char smem[];
    const uint32_t sb = smem_u32(smem);
    const int q0 = qt * 128, k0 = kt * 128;

    float acc[4][4][4] = {};
    const size_t ao = (size_t)(b * S_ + q0) * A_;
    const size_t bo = (size_t)(b * S_ + k0) * A_;
    mma_loop<128, 2>(sb, g_Qhi + ao, g_Qlo + ao, A_, g_Khi + bo, g_Klo + bo, A_,
                     A_ / 32, acc);

    const int lane = threadIdx.x & 31, wid = threadIdx.x >> 5;
    const int wm = wid & 1, wn = wid >> 1;
    float* P = g_S + (size_t)b * S_ * S_;
    const bool full = (kt < qt);
#pragma unroll
    for (int mi = 0; mi < 4; mi++)
#pragma unroll
        for (int nj = 0; nj < 4; nj++)
#pragma unroll
            for (int h = 0; h < 2; h++) {
                int q = q0 + wm * 64 + mi * 16 + (lane >> 2) + h * 8;
                int k = k0 + wn * 32 + nj * 8 + (lane & 3) * 2;
                float v0 = acc[mi][nj][h * 2 + 0];
                float v1 = acc[mi][nj][h * 2 + 1];
                if (full) {
                    *(float2*)(P + (size_t)q * S_ + k) = make_float2(v0, v1);
                } else {
                    if (k <= q)     P[(size_t)q * S_ + k] = v0;
                    if (k + 1 <= q) P[(size_t)q * S_ + k + 1] = v1;
                }
            }
}

// ---------------------------------------------------------------------------
// Softmax over prefix [0,q] -> bf16 hi/lo probs; zero-fill only to the
// 128-aligned bound PV reads.
// grid (4096, 4), 256 threads
// ---------------------------------------------------------------------------
__global__ __launch_bounds__(256)
void softmax_kernel() {
    const int q = blockIdx.x, b = blockIdx.y;
    const float* row = g_S + ((size_t)b * S_ + q) * S_;
    __nv_bfloat16* ohi = g_Phi + ((size_t)b * S_ + q) * S_;
    __nv_bfloat16* olo = g_Plo + ((size_t)b * S_ + q) * S_;
    const int len = q + 1;
    const int zend = ((q >> 7) + 1) << 7;
    const int tid = threadIdx.x;

    __shared__ float fbuf[S_];
    __shared__ float red[8];

    float m = -INFINITY;
    for (int i = tid; i < len; i += 256) {
        float v = row[i];
        fbuf[i] = v;
        m = fmaxf(m, v);
    }
#pragma unroll
    for (int o = 16; o; o >>= 1) m = fmaxf(m, __shfl_xor_sync(0xffffffffu, m, o));
    if ((tid & 31) == 0) red[tid >> 5] = m;
    __syncthreads();
    float mm = red[0];
#pragma unroll
    for (int w = 1; w < 8; w++) mm = fmaxf(mm, red[w]);

    float sum = 0.0f;
    for (int i = tid; i < len; i += 256) {
        float e = expf(fbuf[i] - mm);
        fbuf[i] = e;
        sum += e;
    }
#pragma unroll
    for (int o = 16; o; o >>= 1) sum += __shfl_xor_sync(0xffffffffu, sum, o);
    __syncthreads();
    if ((tid & 31) == 0) red[tid >> 5] = sum;
    __syncthreads();
    float tot = 0.0f;
#pragma unroll
    for (int w = 0; w < 8; w++) tot += red[w];
    const float inv = 1.0f / tot;

    const __nv_bfloat16 z = __float2bfloat16(0.0f);
    for (int i = tid; i < len; i += 256) {
        float p = fbuf[i] * inv;
        __nv_bfloat16 h = __float2bfloat16(p);
        ohi[i] = h;
        olo[i] = __float2bfloat16(p - __bfloat162float(h));
    }
    for (int i = len + tid; i < zend; i += 256) { ohi[i] = z; olo[i] = z; }
}

// ---------------------------------------------------------------------------
// PV: out = P @ Vt^T (128q x 256a per CTA), causal k-bound, round(.,4).
// 4-stage single-sync ring. grid (4 at, 32 qt, 4 b), 256 threads
// ---------------------------------------------------------------------------
__global__ __launch_bounds__(256, 1)
void pv_mma_kernel(float* __restrict__ out) {
    const int at = blockIdx.x, qt = blockIdx.y, b = blockIdx.z;
    extern __shared__ char smem[];
    const uint32_t sb = smem_u32(smem);
    const int q0 = qt * 128, n0 = at * 256;

    float acc[4][8][4] = {};
    const size_t ao = (size_t)(b * S_ + q0) * S_;
    const size_t bo = ((size_t)b * A_ + n0) * S_;
    mma_loop<256, 4>(sb, g_Phi + ao, g_Plo + ao, S_, g_Vthi + bo, g_Vtlo + bo, S_,
                     (qt + 1) * 4, acc);

    const int lane = threadIdx.x & 31, wid = threadIdx.x >> 5;
    const int wm = wid & 1, wn = wid >> 1;
#pragma unroll
    for (int mi = 0; mi < 4; mi++)
#pragma unroll
        for (int nj = 0; nj < 8; nj++)
#pragma unroll
            for (int h = 0; h < 2; h++) {
                int r = q0 + wm * 64 + mi * 16 + (lane >> 2) + h * 8;
                int cc = n0 + wn * 64 + nj * 8 + (lane & 3) * 2;
                float v0 = rintf(acc[mi][nj][h * 2 + 0] * 1e4f) * 1e-4f;
                float v1 = rintf(acc[mi][nj][h * 2 + 1] * 1e4f) * 1e-4f;
                *(float2*)(out + (size_t)(b * S_ + r) * A_ + cc) = make_float2(v0, v1);
            }
}

// ---------------------------------------------------------------------------
// Conversions
// ---------------------------------------------------------------------------
__global__ __launch_bounds__(256)
void cvt_x_kernel(const float* __restrict__ src) {
    int i = (blockIdx.x * 256 + threadIdx.x) * 4;
    float4 v = *(const float4*)(src + i);
    __nv_bfloat162 h0, h1, l0, l1;
    h0.x = __float2bfloat16(v.x); h0.y = __float2bfloat16(v.y);
    h1.x = __float2bfloat16(v.z); h1.y = __float2bfloat16(v.w);
    l0.x = __float2bfloat16(v.x - __bfloat162float(h0.x));
    l0.y = __float2bfloat16(v.y - __bfloat162float(h0.y));
    l1.x = __float2bfloat16(v.z - __bfloat162float(h1.x));
    l1.y = __float2bfloat16(v.w - __bfloat162float(h1.y));
    *(__nv_bfloat162*)(g_Xhi + i) = h0;
    *(__nv_bfloat162*)(g_Xhi + i + 2) = h1;
    *(__nv_bfloat162*)(g_Xlo + i) = l0;
    *(__nv_bfloat162*)(g_Xlo + i + 2) = l1;
}

// Tiled transpose: W[e][a] -> Wt[a][e] hi/lo. grid (32, 32, 3), 256 threads.
__global__ __launch_bounds__(256)
void cvt_w_kernel(const float* __restrict__ Wk, const float* __restrict__ Wq,
                  const float* __restrict__ Wv) {
    const int which = blockIdx.z;
    const float* src = which == 0 ? Wk : (which == 1 ? Wq : Wv);
    const int a0 = blockIdx.x * 32, e0 = blockIdx.y * 32;
    __shared__ float t[32][33];

    const int r = threadIdx.x >> 5, c = threadIdx.x & 31;
#pragma unroll
    for (int i = 0; i < 4; i++)
        t[r + i * 8][c] = src[(size_t)(e0 + r + i * 8) * A_ + a0 + c];
    __syncthreads();

    const int r2 = threadIdx.x >> 4, c2 = (threadIdx.x & 15) * 2;
#pragma unroll
    for (int i = 0; i < 2; i++) {
        int ar = r2 + i * 16;
        float v0 = t[c2][ar], v1 = t[c2 + 1][ar];
        __nv_bfloat162 hv, lv;
        hv.x = __float2bfloat16(v0); hv.y = __float2bfloat16(v1);
        lv.x = __float2bfloat16(v0 - __bfloat162float(hv.x));
        lv.y = __float2bfloat16(v1 - __bfloat162float(hv.y));
        size_t off = (size_t)(a0 + ar) * E_ + e0 + c2;
        *(__nv_bfloat162*)(g_Wthi[which] + off) = hv;
        *(__nv_bfloat162*)(g_Wtlo[which] + off) = lv;
    }
}

// ---------------------------------------------------------------------------
extern "C" void kernel_launch(void* const* d_in, const int* in_sizes, int n_in,
                              void* d_out, int out_size) {
    const float* X  = (const float*)d_in[0];
    const float* Wk = (const float*)d_in[1];
    const float* Wq = (const float*)d_in[2];
    const float* Wv = (const float*)d_in[3];
    float* out = (float*)d_out;

    cudaFuncSetAttribute(qkv_mma_kernel,
                         cudaFuncAttributeMaxDynamicSharedMemorySize, SMEM_QKV);
    cudaFuncSetAttribute(scores_mma_kernel,
                         cudaFuncAttributeMaxDynamicSharedMemorySize, SMEM_SCORES);
    cudaFuncSetAttribute(pv_mma_kernel,
                         cudaFuncAttributeMaxDynamicSharedMemorySize, SMEM_PV);

    cvt_x_kernel<<<M_ * E_ / 1024, 256>>>(X);
    cvt_w_kernel<<<dim3(32, 32, 3), 256>>>(Wk, Wq, Wv);

    qkv_mma_kernel<<<dim3(A_ / 128, M_ / 128, 3), 256, SMEM_QKV>>>();
    scores_mma_kernel<<<dim3(S_ / 128, S_ / 128, B_), 256, SMEM_SCORES>>>();
    softmax_kernel<<<dim3(S_, B_), 256>>>();
    pv_mma_kernel<<<dim3(A_ / 256, S_ / 128, B_), 256, SMEM_PV>>>(out);
}